// round 16
// baseline (speedup 1.0000x reference)
#include <cuda_runtime.h>
#include <cuda_fp16.h>
#include <math.h>
#include <stdint.h>

// Problem constants
#define NB    4
#define NS    2048
#define NHID  2048
#define NDOWN 512
#define NUP   1024
#define NH    16
#define NROPE 64
#define NBS   (NB*NS)
#define NX    1152

// ---------------- scratch (device globals, fp16 intermediates) ----------------
__device__ __half g_Xh  [NBS*NHID];
__device__ __half g_cx  [NBS*NX];
__device__ __half g_kcvc[NBS*2048];
__device__ __half g_qcqr[NBS*2048];
__device__ __half g_Qn [NB*NH*NS*128];   // [bh][s][128] fp16, pre-scaled
__device__ __half g_Kn [NB*NH*NS*128];   // [bh][s][128] fp16
__device__ __half g_Vt [NB*NH*64*NS];    // [bh][dv][s]  fp16
__device__ __half g_ao [NBS*NUP];

__device__ __half g_Wx [NX*NHID];
__device__ __half g_Wu1[2048*NDOWN];
__device__ __half g_Wu2[2048*NDOWN];
__device__ __half g_Wfc[NHID*NUP];
__device__ float  g_bx [NX];
__device__ float  g_bu1[2048];
__device__ float  g_bu2[2048];
__device__ float2 g_rope[NS*32];         // (cos, sin) per (s, i2/2)

// ---------------- helpers ----------------
__device__ __forceinline__ void mma_f16_16n8k16(
    float& c0, float& c1, float& c2, float& c3,
    uint32_t a0, uint32_t a1, uint32_t a2, uint32_t a3,
    uint32_t b0, uint32_t b1)
{
    asm volatile(
        "mma.sync.aligned.m16n8k16.row.col.f32.f16.f16.f32 "
        "{%0,%1,%2,%3}, {%4,%5,%6,%7}, {%8,%9}, {%0,%1,%2,%3};"
        : "+f"(c0), "+f"(c1), "+f"(c2), "+f"(c3)
        : "r"(a0), "r"(a1), "r"(a2), "r"(a3), "r"(b0), "r"(b1));
}
__device__ __forceinline__ void cp16(uint32_t saddr, const void* gptr) {
    asm volatile("cp.async.cg.shared.global [%0], [%1], 16;"
                 :: "r"(saddr), "l"(gptr) : "memory");
}
#define CP_COMMIT() asm volatile("cp.async.commit_group;" ::: "memory")
#define CP_WAIT0()  asm volatile("cp.async.wait_group 0;" ::: "memory")

__device__ __forceinline__ uint32_t pack_h2(float a, float b) {
    __half2 h = __halves2half2(__float2half_rn(a), __float2half_rn(b));
    return *(uint32_t*)&h;
}

// ---------------- fused weight prep (fp16 transposed weights + rope table) --------
__device__ __forceinline__ void tr_tile(
    const float* __restrict__ W, int srcN,
    __half* __restrict__ dst, int dstK, int rowbase,
    int nt, int kt, float (*t)[33], int tx, int ty)
{
    const int n0 = nt * 32, k0 = kt * 32;
    #pragma unroll
    for (int i = ty; i < 32; i += 8)
        t[i][tx] = W[(size_t)(k0 + i) * srcN + n0 + tx];
    __syncthreads();
    #pragma unroll
    for (int i = ty; i < 32; i += 8)
        dst[(size_t)(rowbase + n0 + i) * dstK + k0 + tx] = __float2half_rn(t[tx][i]);
}

__global__ __launch_bounds__(256) void wprep(
    const float* __restrict__ X,
    const float* __restrict__ W_dkv, const float* __restrict__ W_dq,
    const float* __restrict__ W_kr,  const float* __restrict__ W_uk,
    const float* __restrict__ W_uv,  const float* __restrict__ W_uq,
    const float* __restrict__ W_qr,  const float* __restrict__ W_fc,
    const float* __restrict__ b_dkv, const float* __restrict__ b_dq,
    const float* __restrict__ b_kr,  const float* __restrict__ b_uk,
    const float* __restrict__ b_uv,  const float* __restrict__ b_uq,
    const float* __restrict__ b_qr)
{
    __shared__ float t[32][33];
    const int tx = threadIdx.x, ty = threadIdx.y;
    const int id = blockIdx.x;

    if (id < 1024) {
        tr_tile(W_dkv, NDOWN, g_Wx, NHID, 0,    id % 16, id / 16, t, tx, ty);
    } else if (id < 2048) {
        int r = id - 1024;
        tr_tile(W_dq,  NDOWN, g_Wx, NHID, 512,  r % 16, r / 16, t, tx, ty);
    } else if (id < 2176) {
        int r = id - 2048;
        tr_tile(W_kr,  NROPE, g_Wx, NHID, 1024, r % 2, r / 2, t, tx, ty);
    } else if (id < 2304) {
        int r = id - 2176;
        int n0 = (r % 2) * 32, k0 = (r / 2) * 32;
        #pragma unroll
        for (int i = ty; i < 32; i += 8)
            g_Wx[(size_t)(1088 + n0 + i) * NHID + k0 + tx] = __float2half_rn(0.0f);
    } else if (id < 2816) {
        int r = id - 2304;
        tr_tile(W_uk, NUP, g_Wu1, NDOWN, 0,    r % 32, r / 32, t, tx, ty);
    } else if (id < 3328) {
        int r = id - 2816;
        tr_tile(W_uv, NUP, g_Wu1, NDOWN, 1024, r % 32, r / 32, t, tx, ty);
    } else if (id < 3840) {
        int r = id - 3328;
        tr_tile(W_uq, NUP, g_Wu2, NDOWN, 0,    r % 32, r / 32, t, tx, ty);
    } else if (id < 4352) {
        int r = id - 3840;
        tr_tile(W_qr, NUP, g_Wu2, NDOWN, 1024, r % 32, r / 32, t, tx, ty);
    } else if (id < 6400) {
        int r = id - 4352;
        tr_tile(W_fc, NHID, g_Wfc, NUP, 0, r % 64, r / 64, t, tx, ty);
    } else if (id < 6404) {
        int base = (id - 6400) * 256 + ty * 32 + tx;
        for (int j = base; j < 5248; j += 1024) {
            if (j < 1152) {
                float v;
                if      (j < 512)  v = b_dkv[j];
                else if (j < 1024) v = b_dq[j - 512];
                else if (j < 1088) v = b_kr[j - 1024];
                else               v = 0.0f;
                g_bx[j] = v;
            } else if (j < 3200) {
                int k = j - 1152;
                g_bu1[k] = (k < 1024) ? b_uk[k] : b_uv[k - 1024];
            } else {
                int k = j - 3200;
                g_bu2[k] = (k < 1024) ? b_uq[k] : b_qr[k - 1024];
            }
        }
    } else if (id < 7428) {
        // X -> fp16 g_Xh
        const int tid = ty * 32 + tx;
        size_t base = ((size_t)(id - 6404) * 4096 + tid) * 4;
        #pragma unroll
        for (int it = 0; it < 16; it++) {
            size_t e4 = base + (size_t)it * 1024;
            float4 v = *(const float4*)(X + e4);
            uint2 o;
            o.x = pack_h2(v.x, v.y);
            o.y = pack_h2(v.z, v.w);
            *(uint2*)(g_Xh + e4) = o;
        }
    } else {
        // rope table: entry per (s, j) with i2 = 2j. 65536 entries / 256 blocks.
        const int tid = ty * 32 + tx;
        int e = (id - 7428) * 256 + tid;    // 0..65535
        int s = e >> 5, j = e & 31;
        int i2 = 2 * j;
        float fr = powf(10000.0f, -((float)i2) / 64.0f);
        float th = (float)s * fr;
        float cs, sn;
        sincosf(th, &sn, &cs);
        float2 r; r.x = cs; r.y = sn;
        g_rope[e] = r;
    }
}

// ---------------- fp16 mma.sync GEMM (cp.async, 2 CTA/SM, K-chunk 64) --------------
#define SH 72                     // smem stride in halves (64 + 8 pad)
#define TBUF (128*SH)             // halves per tile buffer
template<bool HOUT>
__global__ __launch_bounds__(256, 2) void mma_gemm(
    const __half* __restrict__ A, const __half* __restrict__ Wt,
    const float* __restrict__ bias, void* __restrict__ Cv,
    int K, int lda, int ldc,
    const __half* A2, const __half* Wt2, const float* bias2, void* C2)
{
    if (blockIdx.z) { A = A2; Wt = Wt2; bias = bias2; Cv = C2; }

    extern __shared__ __half smh[];
    __half* As = smh;                    // [2][TBUF]
    __half* Bs = smh + 2*TBUF;
    const uint32_t AsU = (uint32_t)__cvta_generic_to_shared(As);
    const uint32_t BsU = (uint32_t)__cvta_generic_to_shared(Bs);

    const int tid = threadIdx.x;
    const int w = tid >> 5, lane = tid & 31;
    const int g = lane >> 2, tig = lane & 3;
    const int wm = (w & 1) * 64;
    const int wn = (w >> 1) * 32;
    const int M0 = blockIdx.y * 128, N0 = blockIdx.x * 128;

    const __half* Ag = A  + (size_t)M0 * lda;
    const __half* Bg = Wt + (size_t)N0 * K;

    float acc[4][4][4];
    #pragma unroll
    for (int mt = 0; mt < 4; mt++)
        #pragma unroll
        for (int nt = 0; nt < 4; nt++)
            #pragma unroll
            for (int q = 0; q < 4; q++) acc[mt][nt][q] = 0.0f;

    {
        #pragma unroll
        for (int it = 0; it < 4; it++) {
            int e = it * 256 + tid;
            int row = e >> 3;
            int k8  = (e & 7) * 8;
            cp16(AsU + (uint32_t)(row * SH + k8) * 2, Ag + (size_t)row * lda + k8);
            cp16(BsU + (uint32_t)(row * SH + k8) * 2, Bg + (size_t)row * K   + k8);
        }
        CP_COMMIT();
        CP_WAIT0();
    }
    __syncthreads();

    const int NC = K >> 6;
    for (int ch = 0; ch < NC; ch++) {
        const int buf = ch & 1;
        const __half* Ab = As + buf * TBUF;
        const __half* Bb = Bs + buf * TBUF;

        const bool more = (ch + 1 < NC);
        if (more) {
            const int kc0 = (ch + 1) * 64;
            const uint32_t au = AsU + (uint32_t)(buf ^ 1) * (TBUF * 2);
            const uint32_t bu = BsU + (uint32_t)(buf ^ 1) * (TBUF * 2);
            #pragma unroll
            for (int it = 0; it < 4; it++) {
                int e = it * 256 + tid;
                int row = e >> 3;
                int k8  = (e & 7) * 8;
                cp16(au + (uint32_t)(row * SH + k8) * 2, Ag + (size_t)row * lda + kc0 + k8);
                cp16(bu + (uint32_t)(row * SH + k8) * 2, Bg + (size_t)row * K   + kc0 + k8);
            }
            CP_COMMIT();
        }

        #pragma unroll
        for (int ks = 0; ks < 4; ks++) {
            const int k0 = ks * 16;
            uint32_t af[4][4], bf[4][2];
            #pragma unroll
            for (int mt = 0; mt < 4; mt++) {
                const __half* p = Ab + (wm + mt * 16 + g) * SH + k0 + 2 * tig;
                af[mt][0] = *(const uint32_t*)(p);
                af[mt][1] = *(const uint32_t*)(p + 8 * SH);
                af[mt][2] = *(const uint32_t*)(p + 8);
                af[mt][3] = *(const uint32_t*)(p + 8 * SH + 8);
            }
            #pragma unroll
            for (int nt = 0; nt < 4; nt++) {
                const __half* p = Bb + (wn + nt * 8 + g) * SH + k0 + 2 * tig;
                bf[nt][0] = *(const uint32_t*)(p);
                bf[nt][1] = *(const uint32_t*)(p + 8);
            }
            #pragma unroll
            for (int mt = 0; mt < 4; mt++)
                #pragma unroll
                for (int nt = 0; nt < 4; nt++)
                    mma_f16_16n8k16(acc[mt][nt][0], acc[mt][nt][1],
                                    acc[mt][nt][2], acc[mt][nt][3],
                                    af[mt][0], af[mt][1], af[mt][2], af[mt][3],
                                    bf[nt][0], bf[nt][1]);
        }

        if (more) CP_WAIT0();
        __syncthreads();
    }

    #pragma unroll
    for (int mt = 0; mt < 4; mt++) {
        const int row = M0 + wm + mt * 16 + g;
        #pragma unroll
        for (int nt = 0; nt < 4; nt++) {
            const int col = N0 + wn + nt * 8 + 2 * tig;
            float b0 = bias[col], b1 = bias[col + 1];
            float v00 = acc[mt][nt][0] + b0, v01 = acc[mt][nt][1] + b1;
            float v10 = acc[mt][nt][2] + b0, v11 = acc[mt][nt][3] + b1;
            if (HOUT) {
                __half* Ch = (__half*)Cv;
                *(uint32_t*)(Ch + (size_t)row * ldc + col)       = pack_h2(v00, v01);
                *(uint32_t*)(Ch + (size_t)(row + 8) * ldc + col) = pack_h2(v10, v11);
            } else {
                float* Cf = (float*)Cv;
                float2 o0; o0.x = v00; o0.y = v01;
                float2 o1; o1.x = v10; o1.y = v11;
                *(float2*)(Cf + (size_t)row * ldc + col)       = o0;
                *(float2*)(Cf + (size_t)(row + 8) * ldc + col) = o1;
            }
        }
    }
}

// ---------------- fused pack: RoPE Q/K (table) + V transpose (all fp16) -----------
__global__ __launch_bounds__(256) void pack_all(
    const __half* __restrict__ kcvc, const __half* __restrict__ qcqr,
    const __half* __restrict__ cx,
    __half* __restrict__ Qn, __half* __restrict__ Kn, __half* __restrict__ Vt)
{
    __shared__ float t[64*65];
    const float SCALEF = 0.051776695296636886f;
    const int st = blockIdx.x;
    const int bh = blockIdx.y;
    const int b  = bh >> 4, h = bh & 15;
    const int s0 = st * 64;
    const int tid = threadIdx.x;

    // V transpose
    #pragma unroll
    for (int it = 0; it < 4; it++) {
        int e = it*256 + tid;
        int sl = e >> 4, dq = (e & 15) * 4;
        const __half* src = kcvc + ((size_t)(b*NS + s0 + sl))*2048 + 1024 + h*64 + dq;
        t[sl*65 + dq + 0] = __half2float(src[0]);
        t[sl*65 + dq + 1] = __half2float(src[1]);
        t[sl*65 + dq + 2] = __half2float(src[2]);
        t[sl*65 + dq + 3] = __half2float(src[3]);
    }
    __syncthreads();
    #pragma unroll
    for (int it = 0; it < 4; it++) {
        int e = it*256 + tid;
        int dv = e >> 4, sq = (e & 15) * 4;
        uint2 o;
        o.x = pack_h2(t[(sq+0)*65 + dv], t[(sq+1)*65 + dv]);
        o.y = pack_h2(t[(sq+2)*65 + dv], t[(sq+3)*65 + dv]);
        *(uint2*)(Vt + ((size_t)bh*64 + dv)*NS + s0 + sq) = o;
    }

    __half* Qo = Qn + ((size_t)bh*NS + s0) * 128;
    __half* Ko = Kn + ((size_t)bh*NS + s0) * 128;
    for (int it = 0; it < 32; it++) {
        int e = it*256 + tid;
        int sl = e >> 7, d = e & 127;
        int s = s0 + sl;
        int row = b*NS + s;
        float kval, qval;
        if (d < 64) {
            kval = __half2float(kcvc[(size_t)row*2048 + h*64 + d]);
            qval = __half2float(qcqr[(size_t)row*2048 + h*64 + d]);
        } else {
            int dd = d - 64;
            int i2 = dd & ~1;
            float2 cssn = g_rope[s*32 + (i2 >> 1)];
            float cs = cssn.x, sn = cssn.y;
            float kx1 = __half2float(cx[(size_t)row*NX + 1024 + i2]);
            float kx2 = __half2float(cx[(size_t)row*NX + 1024 + i2 + 1]);
            float qx1 = __half2float(qcqr[(size_t)row*2048 + 1024 + h*64 + i2]);
            float qx2 = __half2float(qcqr[(size_t)row*2048 + 1024 + h*64 + i2 + 1]);
            if (dd & 1) { kval = kx2*cs + kx1*sn; qval = qx2*cs + qx1*sn; }
            else        { kval = kx1*cs - kx2*sn; qval = qx1*cs - qx2*sn; }
        }
        Ko[e] = __float2half_rn(kval);
        Qo[e] = __float2half_rn(qval * SCALEF);
    }
}

// ---------------- fp16 mma flash attention, double-buffered, 2 CTA/SM ------------
#define KSTRH 136                  // halves
#define VSTRH 72
#define PSTRH 72
#define KBUFH (64*KSTRH)           // 8704 halves
#define VBUFH (64*VSTRH)           // 4608 halves
__global__ __launch_bounds__(256, 2) void attn_mma(
    const __half* __restrict__ Qn, const __half* __restrict__ Kn,
    const __half* __restrict__ Vt, __half* __restrict__ O)
{
    extern __shared__ __half smh[];
    __half* Kb0 = smh;
    __half* Kb1 = smh + KBUFH;
    __half* Vb0 = smh + 2*KBUFH;
    __half* Vb1 = smh + 2*KBUFH + VBUFH;
    __half* Ps  = smh + 2*KBUFH + 2*VBUFH;
    const uint32_t smU = (uint32_t)__cvta_generic_to_shared(smh);

    const int tid = threadIdx.x;
    const int w = tid >> 5, lane = tid & 31;
    const int g = lane >> 2, tig = lane & 3;
    const int qt = (int)gridDim.x - 1 - (int)blockIdx.x;
    const int bh = blockIdx.y;
    const int b = bh >> 4, h = bh & 15;
    const int q0 = qt * 128;
    const int rowbase = q0 + w * 16;

    const __half* KgB = Kn + (size_t)bh * NS * 128;
    const __half* VgB = Vt + (size_t)bh * 64 * NS;

    uint32_t qa[8][4];
    {
        const int qr0 = min(rowbase + g,     NS - 1);
        const int qr1 = min(rowbase + g + 8, NS - 1);
        const __half* Qg  = Qn + ((size_t)bh * NS + qr0) * 128;
        const __half* Qg8 = Qn + ((size_t)bh * NS + qr1) * 128;
        #pragma unroll
        for (int ks = 0; ks < 8; ks++) {
            qa[ks][0] = *(const uint32_t*)(Qg  + 16*ks + 2*tig);
            qa[ks][1] = *(const uint32_t*)(Qg8 + 16*ks + 2*tig);
            qa[ks][2] = *(const uint32_t*)(Qg  + 16*ks + 2*tig + 8);
            qa[ks][3] = *(const uint32_t*)(Qg8 + 16*ks + 2*tig + 8);
        }
    }

    float m0 = -1e30f, m1 = -1e30f, l0 = 0.0f, l1 = 0.0f;
    float of[8][4];
    #pragma unroll
    for (int nf = 0; nf < 8; nf++)
        #pragma unroll
        for (int c = 0; c < 4; c++) of[nf][c] = 0.0f;

    __half* Pw = Ps + w * 16 * PSTRH;
    const int nkt = 2*qt + 2;

    {
        #pragma unroll
        for (int it = 0; it < 4; it++) {
            int e = it*256 + tid;
            int key = e >> 4, d8 = (e & 15) * 8;
            cp16(smU + (uint32_t)(key*KSTRH + d8) * 2, KgB + (size_t)key*128 + d8);
        }
        #pragma unroll
        for (int it = 0; it < 2; it++) {
            int e = it*256 + tid;
            int dv = e >> 3, k8 = (e & 7) * 8;
            cp16(smU + (uint32_t)(2*KBUFH + dv*VSTRH + k8) * 2, VgB + (size_t)dv*NS + k8);
        }
        CP_COMMIT();
        CP_WAIT0();
    }
    __syncthreads();

    for (int kt = 0; kt < nkt; kt++) {
        const int cur = kt & 1;
        const int k0g = kt * 64;
        const __half* Kbc = cur ? Kb1 : Kb0;
        const __half* Vbc = cur ? Vb1 : Vb0;

        const bool more = (kt + 1 < nkt);
        if (more) {
            const int kn0 = k0g + 64;
            const uint32_t kbU = smU + (uint32_t)((cur ^ 1) ? KBUFH*2 : 0);
            const uint32_t vbU = smU + (uint32_t)(2*KBUFH + ((cur ^ 1) ? VBUFH : 0)) * 2;
            #pragma unroll
            for (int it = 0; it < 4; it++) {
                int e = it*256 + tid;
                int key = e >> 4, d8 = (e & 15) * 8;
                int krow = min(kn0 + key, NS - 1);
                cp16(kbU + (uint32_t)(key*KSTRH + d8) * 2, KgB + (size_t)krow*128 + d8);
            }
            #pragma unroll
            for (int it = 0; it < 2; it++) {
                int e = it*256 + tid;
                int dv = e >> 3, k8 = (e & 7) * 8;
                int kcol = min(kn0 + k8, NS - 8);
                cp16(vbU + (uint32_t)(dv*VSTRH + k8) * 2, VgB + (size_t)dv*NS + kcol);
            }
            CP_COMMIT();
        }

        float sf[8][4];
        #pragma unroll
        for (int nf = 0; nf < 8; nf++)
            #pragma unroll
            for (int c = 0; c < 4; c++) sf[nf][c] = 0.0f;

        #pragma unroll
        for (int ks = 0; ks < 8; ks++) {
            #pragma unroll
            for (int nf = 0; nf < 8; nf++) {
                const __half* bp = Kbc + (nf*8 + g)*KSTRH + 16*ks + 2*tig;
                uint32_t b0 = *(const uint32_t*)(bp);
                uint32_t b1 = *(const uint32_t*)(bp + 8);
                mma_f16_16n8k16(sf[nf][0], sf[nf][1], sf[nf][2], sf[nf][3],
                                qa[ks][0], qa[ks][1], qa[ks][2], qa[ks][3], b0, b1);
            }
        }

        const int row0 = rowbase + g, row1 = row0 + 8;
        if (k0g + 63 > rowbase) {
            #pragma unroll
            for (int nf = 0; nf < 8; nf++) {
                int col = k0g + nf*8 + 2*tig;
                if (col     > row0) sf[nf][0] = -1e9f;
                if (col + 1 > row0) sf[nf][1] = -1e9f;
                if (col     > row1) sf[nf][2] = -1e9f;
                if (col + 1 > row1) sf[nf][3] = -1e9f;
            }
        }
        float mx0 = -1e30f, mx1 = -1e30f;
        #pragma unroll
        for (int nf = 0; nf < 8; nf++) {
            mx0 = fmaxf(mx0, fmaxf(sf[nf][0], sf[nf][1]));
            mx1 = fmaxf(mx1, fmaxf(sf[nf][2], sf[nf][3]));
        }
        mx0 = fmaxf(mx0, __shfl_xor_sync(0xffffffffu, mx0, 1));
        mx0 = fmaxf(mx0, __shfl_xor_sync(0xffffffffu, mx0, 2));
        mx1 = fmaxf(mx1, __shfl_xor_sync(0xffffffffu, mx1, 1));
        mx1 = fmaxf(mx1, __shfl_xor_sync(0xffffffffu, mx1, 2));
        float mn0 = fmaxf(m0, mx0), mn1 = fmaxf(m1, mx1);
        float cr0 = __expf(m0 - mn0), cr1 = __expf(m1 - mn1);
        float ps0 = 0.0f, ps1 = 0.0f;
        #pragma unroll
        for (int nf = 0; nf < 8; nf++) {
            sf[nf][0] = __expf(sf[nf][0] - mn0);
            sf[nf][1] = __expf(sf[nf][1] - mn0);
            sf[nf][2] = __expf(sf[nf][2] - mn1);
            sf[nf][3] = __expf(sf[nf][3] - mn1);
            ps0 += sf[nf][0] + sf[nf][1];
            ps1 += sf[nf][2] + sf[nf][3];
        }
        ps0 += __shfl_xor_sync(0xffffffffu, ps0, 1);
        ps0 += __shfl_xor_sync(0xffffffffu, ps0, 2);
        ps1 += __shfl_xor_sync(0xffffffffu, ps1, 1);
        ps1 += __shfl_xor_sync(0xffffffffu, ps1, 2);
        l0 = l0*cr0 + ps0;  m0 = mn0;
        l1 = l1*cr1 + ps1;  m1 = mn1;

        #pragma unroll
        for (int nf = 0; nf < 8; nf++) {
            of[nf][0] *= cr0; of[nf][1] *= cr0;
            of[nf][2] *= cr1; of[nf][3] *= cr1;
            int col = nf*8 + 2*tig;
            *(uint32_t*)(Pw + g*PSTRH + col)     = pack_h2(sf[nf][0], sf[nf][1]);
            *(uint32_t*)(Pw + (g+8)*PSTRH + col) = pack_h2(sf[nf][2], sf[nf][3]);
        }
        __syncwarp();

        #pragma unroll
        for (int ks = 0; ks < 4; ks++) {
            const __half* pp0 = Pw + g*PSTRH     + 16*ks + 2*tig;
            const __half* pp1 = Pw + (g+8)*PSTRH + 16*ks + 2*tig;
            uint32_t a0 = *(const uint32_t*)(pp0);
            uint32_t a1 = *(const uint32_t*)(pp1);
            uint32_t a2 = *(const uint32_t*)(pp0 + 8);
            uint32_t a3 = *(const uint32_t*)(pp1 + 8);
            #pragma unroll
            for (int nf = 0; nf < 8; nf++) {
                const __half* vp = Vbc + (nf*8 + g)*VSTRH + 16*ks + 2*tig;
                uint32_t b0 = *(const uint32_t*)(vp);
                uint32_t b1 = *(const uint32_t*)(vp + 8);
                mma_f16_16n8k16(of[nf][0], of[nf][1], of[nf][2], of[nf][3],
                                a0, a1, a2, a3, b0, b1);
            }
        }

        if (more) CP_WAIT0();
        __syncthreads();
    }

    const float inv0 = 1.0f / l0, inv1 = 1.0f / l1;
    const int tok0 = b*NS + rowbase + g;
    #pragma unroll
    for (int nf = 0; nf < 8; nf++) {
        int col = h*64 + nf*8 + 2*tig;
        *(uint32_t*)(O + (size_t)tok0 * NUP + col)     = pack_h2(of[nf][0]*inv0, of[nf][1]*inv0);
        *(uint32_t*)(O + (size_t)(tok0+8) * NUP + col) = pack_h2(of[nf][2]*inv1, of[nf][3]*inv1);
    }
}

// ---------------- host launcher ----------------
extern "C" void kernel_launch(void* const* d_in, const int* in_sizes, int n_in,
                              void* d_out, int out_size)
{
    (void)in_sizes; (void)n_in; (void)out_size;
    const float* X     = (const float*)d_in[0];
    const float* W_dkv = (const float*)d_in[2];
    const float* b_dkv = (const float*)d_in[3];
    const float* W_dq  = (const float*)d_in[4];
    const float* b_dq  = (const float*)d_in[5];
    const float* W_uk  = (const float*)d_in[6];
    const float* b_uk  = (const float*)d_in[7];
    const float* W_uv  = (const float*)d_in[8];
    const float* b_uv  = (const float*)d_in[9];
    const float* W_uq  = (const float*)d_in[10];
    const float* b_uq  = (const float*)d_in[11];
    const float* W_qr  = (const float*)d_in[12];
    const float* b_qr  = (const float*)d_in[13];
    const float* W_kr  = (const float*)d_in[14];
    const float* b_kr  = (const float*)d_in[15];
    const float* W_fc  = (const float*)d_in[16];
    const float* b_fc  = (const float*)d_in[17];
    float* out = (float*)d_out;

    __half *Xh, *cx, *kcvc, *qcqr, *Qn, *Kn, *Vt, *ao;
    __half *Wx, *Wu1, *Wu2, *Wfc;
    float *bx, *bu1, *bu2;
    cudaGetSymbolAddress((void**)&Xh,   g_Xh);
    cudaGetSymbolAddress((void**)&cx,   g_cx);
    cudaGetSymbolAddress((void**)&kcvc, g_kcvc);
    cudaGetSymbolAddress((void**)&qcqr, g_qcqr);
    cudaGetSymbolAddress((void**)&Qn,   g_Qn);
    cudaGetSymbolAddress((void**)&Kn,   g_Kn);
    cudaGetSymbolAddress((void**)&Vt,   g_Vt);
    cudaGetSymbolAddress((void**)&ao,   g_ao);
    cudaGetSymbolAddress((void**)&Wx,   g_Wx);
    cudaGetSymbolAddress((void**)&Wu1,  g_Wu1);
    cudaGetSymbolAddress((void**)&Wu2,  g_Wu2);
    cudaGetSymbolAddress((void**)&Wfc,  g_Wfc);
    cudaGetSymbolAddress((void**)&bx,   g_bx);
    cudaGetSymbolAddress((void**)&bu1,  g_bu1);
    cudaGetSymbolAddress((void**)&bu2,  g_bu2);

    // [0] weight prep + X fp16 conversion + rope table
    wprep<<<7684, dim3(32, 8)>>>(X, W_dkv, W_dq, W_kr, W_uk, W_uv, W_uq, W_qr, W_fc,
                                 b_dkv, b_dq, b_kr, b_uk, b_uv, b_uq, b_qr);

    const int GSM = 4 * TBUF * 2;   // 73728 bytes
    cudaFuncSetAttribute(mma_gemm<true>,  cudaFuncAttributeMaxDynamicSharedMemorySize, GSM);
    cudaFuncSetAttribute(mma_gemm<false>, cudaFuncAttributeMaxDynamicSharedMemorySize, GSM);

    // [1] X projections (N=1152)
    mma_gemm<true><<<dim3(NX/128, NBS/128, 1), 256, GSM>>>(
        Xh, Wx, bx, cx, NHID, NHID, NX, nullptr, nullptr, nullptr, nullptr);
    // [2] merged up-projections (z=0: kcvc, z=1: qcqr)
    mma_gemm<true><<<dim3(16, NBS/128, 2), 256, GSM>>>(
        cx, Wu1, bu1, kcvc, NDOWN, NX, 2048, cx + 512, Wu2, bu2, qcqr);

    // [3] fused pack
    pack_all<<<dim3(32, 64), 256>>>(kcvc, qcqr, cx, Qn, Kn, Vt);

    // [4] attention (2 CTA/SM)
    const int ASM = (2*KBUFH + 2*VBUFH + 8*16*PSTRH) * 2;   // 71680 bytes
    cudaFuncSetAttribute(attn_mma, cudaFuncAttributeMaxDynamicSharedMemorySize, ASM);
    attn_mma<<<dim3(16, 64), 256, ASM>>>(Qn, Kn, Vt, ao);

    // [5] final projection (fp32 out)
    mma_gemm<false><<<dim3(16, NBS/128, 1), 256, GSM>>>(
        ao, Wfc, b_fc, out, NUP, NUP, 2048, nullptr, nullptr, nullptr, nullptr);
}

// round 17
// speedup vs baseline: 1.0751x; 1.0751x over previous
#include <cuda_runtime.h>
#include <cuda_fp16.h>
#include <math.h>
#include <stdint.h>

// Problem constants
#define NB    4
#define NS    2048
#define NHID  2048
#define NDOWN 512
#define NUP   1024
#define NH    16
#define NROPE 64
#define NBS   (NB*NS)
#define NX    1152

// ---------------- scratch (device globals, fp16 intermediates) ----------------
__device__ __half g_Xh  [NBS*NHID];
__device__ __half g_cx  [NBS*NX];
__device__ __half g_kcvc[NBS*2048];
__device__ __half g_qcqr[NBS*2048];
__device__ __half g_Qn [NB*NH*NS*128];   // [bh][s][128] fp16, pre-scaled
__device__ __half g_Kn [NB*NH*NS*128];   // [bh][s][128] fp16
__device__ __half g_Vt [NB*NH*64*NS];    // [bh][dv][s]  fp16
__device__ __half g_ao [NBS*NUP];

__device__ __half g_Wx [NX*NHID];
__device__ __half g_Wu1[2048*NDOWN];
__device__ __half g_Wu2[2048*NDOWN];
__device__ __half g_Wfc[NHID*NUP];
__device__ float  g_bx [NX];
__device__ float  g_bu1[2048];
__device__ float  g_bu2[2048];
__device__ float2 g_rope[NS*32];         // (cos, sin) per (s, i2/2)

// ---------------- helpers ----------------
__device__ __forceinline__ void mma_f16_16n8k16(
    float& c0, float& c1, float& c2, float& c3,
    uint32_t a0, uint32_t a1, uint32_t a2, uint32_t a3,
    uint32_t b0, uint32_t b1)
{
    asm volatile(
        "mma.sync.aligned.m16n8k16.row.col.f32.f16.f16.f32 "
        "{%0,%1,%2,%3}, {%4,%5,%6,%7}, {%8,%9}, {%0,%1,%2,%3};"
        : "+f"(c0), "+f"(c1), "+f"(c2), "+f"(c3)
        : "r"(a0), "r"(a1), "r"(a2), "r"(a3), "r"(b0), "r"(b1));
}
__device__ __forceinline__ void ldsm_x4(
    uint32_t& r0, uint32_t& r1, uint32_t& r2, uint32_t& r3, uint32_t saddr)
{
    asm volatile("ldmatrix.sync.aligned.m8n8.x4.shared.b16 {%0,%1,%2,%3}, [%4];"
                 : "=r"(r0), "=r"(r1), "=r"(r2), "=r"(r3) : "r"(saddr));
}
__device__ __forceinline__ void cp16(uint32_t saddr, const void* gptr) {
    asm volatile("cp.async.cg.shared.global [%0], [%1], 16;"
                 :: "r"(saddr), "l"(gptr) : "memory");
}
#define CP_COMMIT() asm volatile("cp.async.commit_group;" ::: "memory")
#define CP_WAIT0()  asm volatile("cp.async.wait_group 0;" ::: "memory")

__device__ __forceinline__ uint32_t pack_h2(float a, float b) {
    __half2 h = __halves2half2(__float2half_rn(a), __float2half_rn(b));
    return *(uint32_t*)&h;
}

// ---------------- fused weight prep (fp16 transposed weights + rope table) --------
__device__ __forceinline__ void tr_tile(
    const float* __restrict__ W, int srcN,
    __half* __restrict__ dst, int dstK, int rowbase,
    int nt, int kt, float (*t)[33], int tx, int ty)
{
    const int n0 = nt * 32, k0 = kt * 32;
    #pragma unroll
    for (int i = ty; i < 32; i += 8)
        t[i][tx] = W[(size_t)(k0 + i) * srcN + n0 + tx];
    __syncthreads();
    #pragma unroll
    for (int i = ty; i < 32; i += 8)
        dst[(size_t)(rowbase + n0 + i) * dstK + k0 + tx] = __float2half_rn(t[tx][i]);
}

__global__ __launch_bounds__(256) void wprep(
    const float* __restrict__ X,
    const float* __restrict__ W_dkv, const float* __restrict__ W_dq,
    const float* __restrict__ W_kr,  const float* __restrict__ W_uk,
    const float* __restrict__ W_uv,  const float* __restrict__ W_uq,
    const float* __restrict__ W_qr,  const float* __restrict__ W_fc,
    const float* __restrict__ b_dkv, const float* __restrict__ b_dq,
    const float* __restrict__ b_kr,  const float* __restrict__ b_uk,
    const float* __restrict__ b_uv,  const float* __restrict__ b_uq,
    const float* __restrict__ b_qr)
{
    __shared__ float t[32][33];
    const int tx = threadIdx.x, ty = threadIdx.y;
    const int id = blockIdx.x;

    if (id < 1024) {
        tr_tile(W_dkv, NDOWN, g_Wx, NHID, 0,    id % 16, id / 16, t, tx, ty);
    } else if (id < 2048) {
        int r = id - 1024;
        tr_tile(W_dq,  NDOWN, g_Wx, NHID, 512,  r % 16, r / 16, t, tx, ty);
    } else if (id < 2176) {
        int r = id - 2048;
        tr_tile(W_kr,  NROPE, g_Wx, NHID, 1024, r % 2, r / 2, t, tx, ty);
    } else if (id < 2304) {
        int r = id - 2176;
        int n0 = (r % 2) * 32, k0 = (r / 2) * 32;
        #pragma unroll
        for (int i = ty; i < 32; i += 8)
            g_Wx[(size_t)(1088 + n0 + i) * NHID + k0 + tx] = __float2half_rn(0.0f);
    } else if (id < 2816) {
        int r = id - 2304;
        tr_tile(W_uk, NUP, g_Wu1, NDOWN, 0,    r % 32, r / 32, t, tx, ty);
    } else if (id < 3328) {
        int r = id - 2816;
        tr_tile(W_uv, NUP, g_Wu1, NDOWN, 1024, r % 32, r / 32, t, tx, ty);
    } else if (id < 3840) {
        int r = id - 3328;
        tr_tile(W_uq, NUP, g_Wu2, NDOWN, 0,    r % 32, r / 32, t, tx, ty);
    } else if (id < 4352) {
        int r = id - 3840;
        tr_tile(W_qr, NUP, g_Wu2, NDOWN, 1024, r % 32, r / 32, t, tx, ty);
    } else if (id < 6400) {
        int r = id - 4352;
        tr_tile(W_fc, NHID, g_Wfc, NUP, 0, r % 64, r / 64, t, tx, ty);
    } else if (id < 6404) {
        int base = (id - 6400) * 256 + ty * 32 + tx;
        for (int j = base; j < 5248; j += 1024) {
            if (j < 1152) {
                float v;
                if      (j < 512)  v = b_dkv[j];
                else if (j < 1024) v = b_dq[j - 512];
                else if (j < 1088) v = b_kr[j - 1024];
                else               v = 0.0f;
                g_bx[j] = v;
            } else if (j < 3200) {
                int k = j - 1152;
                g_bu1[k] = (k < 1024) ? b_uk[k] : b_uv[k - 1024];
            } else {
                int k = j - 3200;
                g_bu2[k] = (k < 1024) ? b_uq[k] : b_qr[k - 1024];
            }
        }
    } else if (id < 7428) {
        const int tid = ty * 32 + tx;
        size_t base = ((size_t)(id - 6404) * 4096 + tid) * 4;
        #pragma unroll
        for (int it = 0; it < 16; it++) {
            size_t e4 = base + (size_t)it * 1024;
            float4 v = *(const float4*)(X + e4);
            uint2 o;
            o.x = pack_h2(v.x, v.y);
            o.y = pack_h2(v.z, v.w);
            *(uint2*)(g_Xh + e4) = o;
        }
    } else {
        const int tid = ty * 32 + tx;
        int e = (id - 7428) * 256 + tid;    // 0..65535
        int s = e >> 5, j = e & 31;
        int i2 = 2 * j;
        float fr = powf(10000.0f, -((float)i2) / 64.0f);
        float th = (float)s * fr;
        float cs, sn;
        sincosf(th, &sn, &cs);
        float2 r; r.x = cs; r.y = sn;
        g_rope[e] = r;
    }
}

// ---------------- fp16 mma.sync GEMM (cp.async, ldmatrix, 2 CTA/SM, K-chunk 64) ----
#define SH 72                     // smem stride in halves (64 + 8 pad)
#define TBUF (128*SH)             // halves per tile buffer
template<bool HOUT>
__global__ __launch_bounds__(256, 2) void mma_gemm(
    const __half* __restrict__ A, const __half* __restrict__ Wt,
    const float* __restrict__ bias, void* __restrict__ Cv,
    int K, int lda, int ldc,
    const __half* A2, const __half* Wt2, const float* bias2, void* C2)
{
    if (blockIdx.z) { A = A2; Wt = Wt2; bias = bias2; Cv = C2; }

    extern __shared__ __half smh[];
    const uint32_t AsU = (uint32_t)__cvta_generic_to_shared(smh);
    const uint32_t BsU = AsU + 2 * TBUF * 2;

    const int tid = threadIdx.x;
    const int w = tid >> 5, lane = tid & 31;
    const int g = lane >> 2, tig = lane & 3;
    const int wm = (w & 1) * 64;
    const int wn = (w >> 1) * 32;
    const int M0 = blockIdx.y * 128, N0 = blockIdx.x * 128;

    // ldmatrix per-lane row/k offsets (halves)
    const int rA = (lane & 7) + ((lane >> 3) & 1) * 8;
    const int kA = (lane >> 4) * 8;
    const int rB = (lane & 7) + ((lane >> 4) & 1) * 8;
    const int kB = ((lane >> 3) & 1) * 8;

    const __half* Ag = A  + (size_t)M0 * lda;
    const __half* Bg = Wt + (size_t)N0 * K;

    float acc[4][4][4];
    #pragma unroll
    for (int mt = 0; mt < 4; mt++)
        #pragma unroll
        for (int nt = 0; nt < 4; nt++)
            #pragma unroll
            for (int q = 0; q < 4; q++) acc[mt][nt][q] = 0.0f;

    {
        #pragma unroll
        for (int it = 0; it < 4; it++) {
            int e = it * 256 + tid;
            int row = e >> 3;
            int k8  = (e & 7) * 8;
            cp16(AsU + (uint32_t)(row * SH + k8) * 2, Ag + (size_t)row * lda + k8);
            cp16(BsU + (uint32_t)(row * SH + k8) * 2, Bg + (size_t)row * K   + k8);
        }
        CP_COMMIT();
        CP_WAIT0();
    }
    __syncthreads();

    const int NC = K >> 6;
    for (int ch = 0; ch < NC; ch++) {
        const int buf = ch & 1;
        const uint32_t AbU = AsU + (uint32_t)buf * (TBUF * 2);
        const uint32_t BbU = BsU + (uint32_t)buf * (TBUF * 2);

        const bool more = (ch + 1 < NC);
        if (more) {
            const int kc0 = (ch + 1) * 64;
            const uint32_t au = AsU + (uint32_t)(buf ^ 1) * (TBUF * 2);
            const uint32_t bu = BsU + (uint32_t)(buf ^ 1) * (TBUF * 2);
            #pragma unroll
            for (int it = 0; it < 4; it++) {
                int e = it * 256 + tid;
                int row = e >> 3;
                int k8  = (e & 7) * 8;
                cp16(au + (uint32_t)(row * SH + k8) * 2, Ag + (size_t)row * lda + kc0 + k8);
                cp16(bu + (uint32_t)(row * SH + k8) * 2, Bg + (size_t)row * K   + kc0 + k8);
            }
            CP_COMMIT();
        }

        #pragma unroll
        for (int ks = 0; ks < 4; ks++) {
            const int k0 = ks * 16;
            uint32_t af[4][4], bf[4][2];
            #pragma unroll
            for (int mt = 0; mt < 4; mt++)
                ldsm_x4(af[mt][0], af[mt][1], af[mt][2], af[mt][3],
                        AbU + (uint32_t)((wm + mt * 16 + rA) * SH + k0 + kA) * 2);
            #pragma unroll
            for (int np = 0; np < 2; np++)
                ldsm_x4(bf[2*np][0], bf[2*np][1], bf[2*np+1][0], bf[2*np+1][1],
                        BbU + (uint32_t)((wn + np * 16 + rB) * SH + k0 + kB) * 2);
            #pragma unroll
            for (int mt = 0; mt < 4; mt++)
                #pragma unroll
                for (int nt = 0; nt < 4; nt++)
                    mma_f16_16n8k16(acc[mt][nt][0], acc[mt][nt][1],
                                    acc[mt][nt][2], acc[mt][nt][3],
                                    af[mt][0], af[mt][1], af[mt][2], af[mt][3],
                                    bf[nt][0], bf[nt][1]);
        }

        if (more) CP_WAIT0();
        __syncthreads();
    }

    #pragma unroll
    for (int mt = 0; mt < 4; mt++) {
        const int row = M0 + wm + mt * 16 + g;
        #pragma unroll
        for (int nt = 0; nt < 4; nt++) {
            const int col = N0 + wn + nt * 8 + 2 * tig;
            float b0 = bias[col], b1 = bias[col + 1];
            float v00 = acc[mt][nt][0] + b0, v01 = acc[mt][nt][1] + b1;
            float v10 = acc[mt][nt][2] + b0, v11 = acc[mt][nt][3] + b1;
            if (HOUT) {
                __half* Ch = (__half*)Cv;
                *(uint32_t*)(Ch + (size_t)row * ldc + col)       = pack_h2(v00, v01);
                *(uint32_t*)(Ch + (size_t)(row + 8) * ldc + col) = pack_h2(v10, v11);
            } else {
                float* Cf = (float*)Cv;
                float2 o0; o0.x = v00; o0.y = v01;
                float2 o1; o1.x = v10; o1.y = v11;
                *(float2*)(Cf + (size_t)row * ldc + col)       = o0;
                *(float2*)(Cf + (size_t)(row + 8) * ldc + col) = o1;
            }
        }
    }
}

// ---------------- fused pack: RoPE Q/K (table) + V transpose (all fp16) -----------
__global__ __launch_bounds__(256) void pack_all(
    const __half* __restrict__ kcvc, const __half* __restrict__ qcqr,
    const __half* __restrict__ cx,
    __half* __restrict__ Qn, __half* __restrict__ Kn, __half* __restrict__ Vt)
{
    __shared__ float t[64*65];
    const float SCALEF = 0.051776695296636886f;
    const int st = blockIdx.x;
    const int bh = blockIdx.y;
    const int b  = bh >> 4, h = bh & 15;
    const int s0 = st * 64;
    const int tid = threadIdx.x;

    #pragma unroll
    for (int it = 0; it < 4; it++) {
        int e = it*256 + tid;
        int sl = e >> 4, dq = (e & 15) * 4;
        const __half* src = kcvc + ((size_t)(b*NS + s0 + sl))*2048 + 1024 + h*64 + dq;
        t[sl*65 + dq + 0] = __half2float(src[0]);
        t[sl*65 + dq + 1] = __half2float(src[1]);
        t[sl*65 + dq + 2] = __half2float(src[2]);
        t[sl*65 + dq + 3] = __half2float(src[3]);
    }
    __syncthreads();
    #pragma unroll
    for (int it = 0; it < 4; it++) {
        int e = it*256 + tid;
        int dv = e >> 4, sq = (e & 15) * 4;
        uint2 o;
        o.x = pack_h2(t[(sq+0)*65 + dv], t[(sq+1)*65 + dv]);
        o.y = pack_h2(t[(sq+2)*65 + dv], t[(sq+3)*65 + dv]);
        *(uint2*)(Vt + ((size_t)bh*64 + dv)*NS + s0 + sq) = o;
    }

    __half* Qo = Qn + ((size_t)bh*NS + s0) * 128;
    __half* Ko = Kn + ((size_t)bh*NS + s0) * 128;
    for (int it = 0; it < 32; it++) {
        int e = it*256 + tid;
        int sl = e >> 7, d = e & 127;
        int s = s0 + sl;
        int row = b*NS + s;
        float kval, qval;
        if (d < 64) {
            kval = __half2float(kcvc[(size_t)row*2048 + h*64 + d]);
            qval = __half2float(qcqr[(size_t)row*2048 + h*64 + d]);
        } else {
            int dd = d - 64;
            int i2 = dd & ~1;
            float2 cssn = g_rope[s*32 + (i2 >> 1)];
            float cs = cssn.x, sn = cssn.y;
            float kx1 = __half2float(cx[(size_t)row*NX + 1024 + i2]);
            float kx2 = __half2float(cx[(size_t)row*NX + 1024 + i2 + 1]);
            float qx1 = __half2float(qcqr[(size_t)row*2048 + 1024 + h*64 + i2]);
            float qx2 = __half2float(qcqr[(size_t)row*2048 + 1024 + h*64 + i2 + 1]);
            if (dd & 1) { kval = kx2*cs + kx1*sn; qval = qx2*cs + qx1*sn; }
            else        { kval = kx1*cs - kx2*sn; qval = qx1*cs - qx2*sn; }
        }
        Ko[e] = __float2half_rn(kval);
        Qo[e] = __float2half_rn(qval * SCALEF);
    }
}

// ---------------- fp16 mma flash attention (ldmatrix, dbuf, 2 CTA/SM) ------------
#define KSTRH 136                  // halves
#define VSTRH 72
#define PSTRH 72
#define KBUFH (64*KSTRH)           // 8704 halves
#define VBUFH (64*VSTRH)           // 4608 halves
__global__ __launch_bounds__(256, 2) void attn_mma(
    const __half* __restrict__ Qn, const __half* __restrict__ Kn,
    const __half* __restrict__ Vt, __half* __restrict__ O)
{
    extern __shared__ __half smh[];
    const uint32_t smU = (uint32_t)__cvta_generic_to_shared(smh);
    __half* Pw;

    const int tid = threadIdx.x;
    const int w = tid >> 5, lane = tid & 31;
    const int g = lane >> 2, tig = lane & 3;
    const int qt = (int)gridDim.x - 1 - (int)blockIdx.x;
    const int bh = blockIdx.y;
    const int b = bh >> 4, h = bh & 15;
    const int q0 = qt * 128;
    const int rowbase = q0 + w * 16;

    // ldmatrix per-lane offsets (halves)
    const int rA = (lane & 7) + ((lane >> 3) & 1) * 8;
    const int kA = (lane >> 4) * 8;
    const int rB = (lane & 7) + ((lane >> 4) & 1) * 8;
    const int kB = ((lane >> 3) & 1) * 8;

    const uint32_t PwU = smU + (uint32_t)(2*KBUFH + 2*VBUFH + w * 16 * PSTRH) * 2;
    Pw = smh + 2*KBUFH + 2*VBUFH + w * 16 * PSTRH;

    const __half* KgB = Kn + (size_t)bh * NS * 128;
    const __half* VgB = Vt + (size_t)bh * 64 * NS;

    uint32_t qa[8][4];
    {
        const int qr0 = min(rowbase + g,     NS - 1);
        const int qr1 = min(rowbase + g + 8, NS - 1);
        const __half* Qg  = Qn + ((size_t)bh * NS + qr0) * 128;
        const __half* Qg8 = Qn + ((size_t)bh * NS + qr1) * 128;
        #pragma unroll
        for (int ks = 0; ks < 8; ks++) {
            qa[ks][0] = *(const uint32_t*)(Qg  + 16*ks + 2*tig);
            qa[ks][1] = *(const uint32_t*)(Qg8 + 16*ks + 2*tig);
            qa[ks][2] = *(const uint32_t*)(Qg  + 16*ks + 2*tig + 8);
            qa[ks][3] = *(const uint32_t*)(Qg8 + 16*ks + 2*tig + 8);
        }
    }

    float m0 = -1e30f, m1 = -1e30f, l0 = 0.0f, l1 = 0.0f;
    float of[8][4];
    #pragma unroll
    for (int nf = 0; nf < 8; nf++)
        #pragma unroll
        for (int c = 0; c < 4; c++) of[nf][c] = 0.0f;

    const int nkt = 2*qt + 2;

    {
        #pragma unroll
        for (int it = 0; it < 4; it++) {
            int e = it*256 + tid;
            int key = e >> 4, d8 = (e & 15) * 8;
            cp16(smU + (uint32_t)(key*KSTRH + d8) * 2, KgB + (size_t)key*128 + d8);
        }
        #pragma unroll
        for (int it = 0; it < 2; it++) {
            int e = it*256 + tid;
            int dv = e >> 3, k8 = (e & 7) * 8;
            cp16(smU + (uint32_t)(2*KBUFH + dv*VSTRH + k8) * 2, VgB + (size_t)dv*NS + k8);
        }
        CP_COMMIT();
        CP_WAIT0();
    }
    __syncthreads();

    for (int kt = 0; kt < nkt; kt++) {
        const int cur = kt & 1;
        const int k0g = kt * 64;
        const uint32_t KbU = smU + (uint32_t)(cur ? KBUFH*2 : 0);
        const uint32_t VbU = smU + (uint32_t)(2*KBUFH + (cur ? VBUFH : 0)) * 2;

        const bool more = (kt + 1 < nkt);
        if (more) {
            const int kn0 = k0g + 64;
            const uint32_t kbU = smU + (uint32_t)((cur ^ 1) ? KBUFH*2 : 0);
            const uint32_t vbU = smU + (uint32_t)(2*KBUFH + ((cur ^ 1) ? VBUFH : 0)) * 2;
            #pragma unroll
            for (int it = 0; it < 4; it++) {
                int e = it*256 + tid;
                int key = e >> 4, d8 = (e & 15) * 8;
                int krow = min(kn0 + key, NS - 1);
                cp16(kbU + (uint32_t)(key*KSTRH + d8) * 2, KgB + (size_t)krow*128 + d8);
            }
            #pragma unroll
            for (int it = 0; it < 2; it++) {
                int e = it*256 + tid;
                int dv = e >> 3, k8 = (e & 7) * 8;
                int kcol = min(kn0 + k8, NS - 8);
                cp16(vbU + (uint32_t)(dv*VSTRH + k8) * 2, VgB + (size_t)dv*NS + kcol);
            }
            CP_COMMIT();
        }

        // ---- S = Q @ K^T (8 k16 steps; K frags via ldmatrix) ----
        float sf[8][4];
        #pragma unroll
        for (int nf = 0; nf < 8; nf++)
            #pragma unroll
            for (int c = 0; c < 4; c++) sf[nf][c] = 0.0f;

        #pragma unroll
        for (int ks = 0; ks < 8; ks++) {
            uint32_t bf[8][2];
            #pragma unroll
            for (int np = 0; np < 4; np++)
                ldsm_x4(bf[2*np][0], bf[2*np][1], bf[2*np+1][0], bf[2*np+1][1],
                        KbU + (uint32_t)((np * 16 + rB) * KSTRH + 16*ks + kB) * 2);
            #pragma unroll
            for (int nf = 0; nf < 8; nf++)
                mma_f16_16n8k16(sf[nf][0], sf[nf][1], sf[nf][2], sf[nf][3],
                                qa[ks][0], qa[ks][1], qa[ks][2], qa[ks][3],
                                bf[nf][0], bf[nf][1]);
        }

        // ---- mask + online softmax ----
        const int row0 = rowbase + g, row1 = row0 + 8;
        if (k0g + 63 > rowbase) {
            #pragma unroll
            for (int nf = 0; nf < 8; nf++) {
                int col = k0g + nf*8 + 2*tig;
                if (col     > row0) sf[nf][0] = -1e9f;
                if (col + 1 > row0) sf[nf][1] = -1e9f;
                if (col     > row1) sf[nf][2] = -1e9f;
                if (col + 1 > row1) sf[nf][3] = -1e9f;
            }
        }
        float mx0 = -1e30f, mx1 = -1e30f;
        #pragma unroll
        for (int nf = 0; nf < 8; nf++) {
            mx0 = fmaxf(mx0, fmaxf(sf[nf][0], sf[nf][1]));
            mx1 = fmaxf(mx1, fmaxf(sf[nf][2], sf[nf][3]));
        }
        mx0 = fmaxf(mx0, __shfl_xor_sync(0xffffffffu, mx0, 1));
        mx0 = fmaxf(mx0, __shfl_xor_sync(0xffffffffu, mx0, 2));
        mx1 = fmaxf(mx1, __shfl_xor_sync(0xffffffffu, mx1, 1));
        mx1 = fmaxf(mx1, __shfl_xor_sync(0xffffffffu, mx1, 2));
        float mn0 = fmaxf(m0, mx0), mn1 = fmaxf(m1, mx1);
        float cr0 = __expf(m0 - mn0), cr1 = __expf(m1 - mn1);
        float ps0 = 0.0f, ps1 = 0.0f;
        #pragma unroll
        for (int nf = 0; nf < 8; nf++) {
            sf[nf][0] = __expf(sf[nf][0] - mn0);
            sf[nf][1] = __expf(sf[nf][1] - mn0);
            sf[nf][2] = __expf(sf[nf][2] - mn1);
            sf[nf][3] = __expf(sf[nf][3] - mn1);
            ps0 += sf[nf][0] + sf[nf][1];
            ps1 += sf[nf][2] + sf[nf][3];
        }
        ps0 += __shfl_xor_sync(0xffffffffu, ps0, 1);
        ps0 += __shfl_xor_sync(0xffffffffu, ps0, 2);
        ps1 += __shfl_xor_sync(0xffffffffu, ps1, 1);
        ps1 += __shfl_xor_sync(0xffffffffu, ps1, 2);
        l0 = l0*cr0 + ps0;  m0 = mn0;
        l1 = l1*cr1 + ps1;  m1 = mn1;

        #pragma unroll
        for (int nf = 0; nf < 8; nf++) {
            of[nf][0] *= cr0; of[nf][1] *= cr0;
            of[nf][2] *= cr1; of[nf][3] *= cr1;
            int col = nf*8 + 2*tig;
            *(uint32_t*)(Pw + g*PSTRH + col)     = pack_h2(sf[nf][0], sf[nf][1]);
            *(uint32_t*)(Pw + (g+8)*PSTRH + col) = pack_h2(sf[nf][2], sf[nf][3]);
        }
        __syncwarp();

        // ---- O += P @ V (4 k16 steps; P and V frags via ldmatrix) ----
        #pragma unroll
        for (int ks = 0; ks < 4; ks++) {
            uint32_t a0, a1, a2, a3;
            ldsm_x4(a0, a1, a2, a3,
                    PwU + (uint32_t)(rA * PSTRH + 16*ks + kA) * 2);
            uint32_t bf[8][2];
            #pragma unroll
            for (int np = 0; np < 4; np++)
                ldsm_x4(bf[2*np][0], bf[2*np][1], bf[2*np+1][0], bf[2*np+1][1],
                        VbU + (uint32_t)((np * 16 + rB) * VSTRH + 16*ks + kB) * 2);
            #pragma unroll
            for (int nf = 0; nf < 8; nf++)
                mma_f16_16n8k16(of[nf][0], of[nf][1], of[nf][2], of[nf][3],
                                a0, a1, a2, a3, bf[nf][0], bf[nf][1]);
        }

        if (more) CP_WAIT0();
        __syncthreads();
    }

    const float inv0 = 1.0f / l0, inv1 = 1.0f / l1;
    const int tok0 = b*NS + rowbase + g;
    #pragma unroll
    for (int nf = 0; nf < 8; nf++) {
        int col = h*64 + nf*8 + 2*tig;
        *(uint32_t*)(O + (size_t)tok0 * NUP + col)     = pack_h2(of[nf][0]*inv0, of[nf][1]*inv0);
        *(uint32_t*)(O + (size_t)(tok0+8) * NUP + col) = pack_h2(of[nf][2]*inv1, of[nf][3]*inv1);
    }
}

// ---------------- host launcher ----------------
extern "C" void kernel_launch(void* const* d_in, const int* in_sizes, int n_in,
                              void* d_out, int out_size)
{
    (void)in_sizes; (void)n_in; (void)out_size;
    const float* X     = (const float*)d_in[0];
    const float* W_dkv = (const float*)d_in[2];
    const float* b_dkv = (const float*)d_in[3];
    const float* W_dq  = (const float*)d_in[4];
    const float* b_dq  = (const float*)d_in[5];
    const float* W_uk  = (const float*)d_in[6];
    const float* b_uk  = (const float*)d_in[7];
    const float* W_uv  = (const float*)d_in[8];
    const float* b_uv  = (const float*)d_in[9];
    const float* W_uq  = (const float*)d_in[10];
    const float* b_uq  = (const float*)d_in[11];
    const float* W_qr  = (const float*)d_in[12];
    const float* b_qr  = (const float*)d_in[13];
    const float* W_kr  = (const float*)d_in[14];
    const float* b_kr  = (const float*)d_in[15];
    const float* W_fc  = (const float*)d_in[16];
    const float* b_fc  = (const float*)d_in[17];
    float* out = (float*)d_out;

    __half *Xh, *cx, *kcvc, *qcqr, *Qn, *Kn, *Vt, *ao;
    __half *Wx, *Wu1, *Wu2, *Wfc;
    float *bx, *bu1, *bu2;
    cudaGetSymbolAddress((void**)&Xh,   g_Xh);
    cudaGetSymbolAddress((void**)&cx,   g_cx);
    cudaGetSymbolAddress((void**)&kcvc, g_kcvc);
    cudaGetSymbolAddress((void**)&qcqr, g_qcqr);
    cudaGetSymbolAddress((void**)&Qn,   g_Qn);
    cudaGetSymbolAddress((void**)&Kn,   g_Kn);
    cudaGetSymbolAddress((void**)&Vt,   g_Vt);
    cudaGetSymbolAddress((void**)&ao,   g_ao);
    cudaGetSymbolAddress((void**)&Wx,   g_Wx);
    cudaGetSymbolAddress((void**)&Wu1,  g_Wu1);
    cudaGetSymbolAddress((void**)&Wu2,  g_Wu2);
    cudaGetSymbolAddress((void**)&Wfc,  g_Wfc);
    cudaGetSymbolAddress((void**)&bx,   g_bx);
    cudaGetSymbolAddress((void**)&bu1,  g_bu1);
    cudaGetSymbolAddress((void**)&bu2,  g_bu2);

    // [0] weight prep + X fp16 conversion + rope table
    wprep<<<7684, dim3(32, 8)>>>(X, W_dkv, W_dq, W_kr, W_uk, W_uv, W_uq, W_qr, W_fc,
                                 b_dkv, b_dq, b_kr, b_uk, b_uv, b_uq, b_qr);

    const int GSM = 4 * TBUF * 2;   // 73728 bytes
    cudaFuncSetAttribute(mma_gemm<true>,  cudaFuncAttributeMaxDynamicSharedMemorySize, GSM);
    cudaFuncSetAttribute(mma_gemm<false>, cudaFuncAttributeMaxDynamicSharedMemorySize, GSM);

    // [1] X projections (N=1152)
    mma_gemm<true><<<dim3(NX/128, NBS/128, 1), 256, GSM>>>(
        Xh, Wx, bx, cx, NHID, NHID, NX, nullptr, nullptr, nullptr, nullptr);
    // [2] merged up-projections (z=0: kcvc, z=1: qcqr)
    mma_gemm<true><<<dim3(16, NBS/128, 2), 256, GSM>>>(
        cx, Wu1, bu1, kcvc, NDOWN, NX, 2048, cx + 512, Wu2, bu2, qcqr);

    // [3] fused pack
    pack_all<<<dim3(32, 64), 256>>>(kcvc, qcqr, cx, Qn, Kn, Vt);

    // [4] attention (2 CTA/SM)
    const int ASM = (2*KBUFH + 2*VBUFH + 8*16*PSTRH) * 2;   // 71680 bytes
    cudaFuncSetAttribute(attn_mma, cudaFuncAttributeMaxDynamicSharedMemorySize, ASM);
    attn_mma<<<dim3(16, 64), 256, ASM>>>(Qn, Kn, Vt, ao);

    // [5] final projection (fp32 out)
    mma_gemm<false><<<dim3(16, NBS/128, 1), 256, GSM>>>(
        ao, Wfc, b_fc, out, NUP, NUP, 2048, nullptr, nullptr, nullptr, nullptr);
}